// round 11
// baseline (speedup 1.0000x reference)
#include <cuda_runtime.h>

// SimilarityMeasureModel on GB300 (sm_103a) — FINAL (held; 6 reproductions).
// Inputs: x, y [B=32, P=3, C=512, N=1024] f32 (N contiguous).
// Per (b,p,n): l1 = sum_c |x-y|, l2 = sum_c (x-y)^2 ; out = [l1,l2,l1] interleaved.
//
// Terminal state: streams the 403.9 MB compulsory traffic at 6.48-6.70 TB/s,
// the measured GB300 memory-path ceiling (LTS chip cap ~6300 B/cyc, path- and
// pattern-independent). Floor: 403.9 MB / 6.7 TB/s + launch ~= 61.3us;
// measured best 61.4us, band 61.4-62.2us across 6 runs (ceiling's own
// run-to-run variance). Zero wasted traffic (HBM rate == compulsory rate).
// Falsified levers: occupancy/backfill (R3: occ 46% -> same BW),
// DRAM row-locality via contiguous per-block streams (R4: slower).
// Confirmed wins: LDG.128 + 4-way C-split (R2: 84.7 -> 62.0us),
// __ldcs/__stcs streaming hints + unroll 8 (R6: 62.0 -> 61.5us).

static constexpr int B = 32;
static constexpr int P = 3;
static constexpr int C = 512;
static constexpr int N = 1024;
static constexpr int N4 = N / 4;          // float4 units per row: 256
static constexpr int SEGS = 4;            // C split
static constexpr int CSEG = C / SEGS;     // 128
static constexpr int NV_PER_BLK = 64;     // float4 groups per block -> 256 n values
static constexpr int BLOCKS = (B * P * N) / (NV_PER_BLK * 4);  // 384

__global__ void __launch_bounds__(256, 4)
sim_measure_kernel(const float4* __restrict__ x,
                   const float4* __restrict__ y,
                   float* __restrict__ out) {
    // Block -> (bp, n-quarter)
    const int bid   = blockIdx.x;
    const int bp    = bid >> 2;                 // 0..95  (b*P + p)
    const int nq    = bid & 3;                  // which 256-n chunk
    const int n4off = nq * NV_PER_BLK;          // float4 offset within row

    const int tid = threadIdx.x;
    const int s   = tid >> 6;                   // C-segment 0..3 (2 warps each)
    const int n4  = tid & 63;                   // float4 index within chunk

    const int n4g = n4off + n4;
    size_t idx = ((size_t)bp * C + (size_t)s * CSEG) * N4 + n4g;

    float4 l1 = make_float4(0.f, 0.f, 0.f, 0.f);
    float4 l2 = make_float4(0.f, 0.f, 0.f, 0.f);

    #pragma unroll 8
    for (int c = 0; c < CSEG; ++c) {
        float4 a = __ldcs(x + idx);   // streaming: evict-first in L2
        float4 b = __ldcs(y + idx);
        idx += N4;
        float d0 = a.x - b.x, d1 = a.y - b.y, d2 = a.z - b.z, d3 = a.w - b.w;
        l1.x += fabsf(d0); l1.y += fabsf(d1); l1.z += fabsf(d2); l1.w += fabsf(d3);
        l2.x = fmaf(d0, d0, l2.x); l2.y = fmaf(d1, d1, l2.y);
        l2.z = fmaf(d2, d2, l2.z); l2.w = fmaf(d3, d3, l2.w);
    }

    // Combine the 4 C-segments through shared memory.
    __shared__ float4 sL1[SEGS][NV_PER_BLK];
    __shared__ float4 sL2[SEGS][NV_PER_BLK];
    sL1[s][n4] = l1;
    sL2[s][n4] = l2;
    __syncthreads();

    // 256 threads -> 256 n values of this block; thread t handles n_local = t.
    const int m4 = tid >> 2;      // which float4 group
    const int j  = tid & 3;       // component

    float a1 = 0.f, a2 = 0.f;
    #pragma unroll
    for (int ss = 0; ss < SEGS; ++ss) {
        const float* p1 = (const float*)&sL1[ss][m4];
        const float* p2 = (const float*)&sL2[ss][m4];
        a1 += p1[j];
        a2 += p2[j];
    }

    // pair index = bp*N + nq*256 + tid ; out layout [l1, l2, l1] per pair
    const size_t pair = (size_t)bp * N + (size_t)nq * 256 + tid;
    const size_t o = pair * 3;
    __stcs(out + o + 0, a1);
    __stcs(out + o + 1, a2);
    __stcs(out + o + 2, a1);
}

extern "C" void kernel_launch(void* const* d_in, const int* in_sizes, int n_in,
                              void* d_out, int out_size) {
    const float4* x = (const float4*)d_in[0];
    const float4* y = (const float4*)d_in[1];
    float* out = (float*)d_out;

    sim_measure_kernel<<<BLOCKS, 256>>>(x, y, out);
}

// round 12
// speedup vs baseline: 1.0062x; 1.0062x over previous
#include <cuda_runtime.h>

// SimilarityMeasureModel on GB300 (sm_103a) — FINAL (held; 7 reproductions).
// Inputs: x, y [B=32, P=3, C=512, N=1024] f32 (N contiguous).
// Per (b,p,n): l1 = sum_c |x-y|, l2 = sum_c (x-y)^2 ; out = [l1,l2,l1] interleaved.
//
// Terminal state: streams the 403.9 MB compulsory traffic at 6.48-6.70 TB/s,
// the measured GB300 memory-path ceiling (LTS chip cap ~6300 B/cyc, path- and
// pattern-independent). Floor: 403.9 MB / 6.7 TB/s + launch ~= 61.3us;
// measured best 61.4us, band 61.4-62.2us across 7 runs (ceiling's own
// run-to-run variance). Zero wasted traffic (HBM rate == compulsory rate).
// Falsified levers: occupancy/backfill (R3: occ 46% -> same BW),
// DRAM row-locality via contiguous per-block streams (R4: slower).
// Confirmed wins: LDG.128 + 4-way C-split (R2: 84.7 -> 62.0us),
// __ldcs/__stcs streaming hints + unroll 8 (R6: 62.0 -> 61.5us).

static constexpr int B = 32;
static constexpr int P = 3;
static constexpr int C = 512;
static constexpr int N = 1024;
static constexpr int N4 = N / 4;          // float4 units per row: 256
static constexpr int SEGS = 4;            // C split
static constexpr int CSEG = C / SEGS;     // 128
static constexpr int NV_PER_BLK = 64;     // float4 groups per block -> 256 n values
static constexpr int BLOCKS = (B * P * N) / (NV_PER_BLK * 4);  // 384

__global__ void __launch_bounds__(256, 4)
sim_measure_kernel(const float4* __restrict__ x,
                   const float4* __restrict__ y,
                   float* __restrict__ out) {
    // Block -> (bp, n-quarter)
    const int bid   = blockIdx.x;
    const int bp    = bid >> 2;                 // 0..95  (b*P + p)
    const int nq    = bid & 3;                  // which 256-n chunk
    const int n4off = nq * NV_PER_BLK;          // float4 offset within row

    const int tid = threadIdx.x;
    const int s   = tid >> 6;                   // C-segment 0..3 (2 warps each)
    const int n4  = tid & 63;                   // float4 index within chunk

    const int n4g = n4off + n4;
    size_t idx = ((size_t)bp * C + (size_t)s * CSEG) * N4 + n4g;

    float4 l1 = make_float4(0.f, 0.f, 0.f, 0.f);
    float4 l2 = make_float4(0.f, 0.f, 0.f, 0.f);

    #pragma unroll 8
    for (int c = 0; c < CSEG; ++c) {
        float4 a = __ldcs(x + idx);   // streaming: evict-first in L2
        float4 b = __ldcs(y + idx);
        idx += N4;
        float d0 = a.x - b.x, d1 = a.y - b.y, d2 = a.z - b.z, d3 = a.w - b.w;
        l1.x += fabsf(d0); l1.y += fabsf(d1); l1.z += fabsf(d2); l1.w += fabsf(d3);
        l2.x = fmaf(d0, d0, l2.x); l2.y = fmaf(d1, d1, l2.y);
        l2.z = fmaf(d2, d2, l2.z); l2.w = fmaf(d3, d3, l2.w);
    }

    // Combine the 4 C-segments through shared memory.
    __shared__ float4 sL1[SEGS][NV_PER_BLK];
    __shared__ float4 sL2[SEGS][NV_PER_BLK];
    sL1[s][n4] = l1;
    sL2[s][n4] = l2;
    __syncthreads();

    // 256 threads -> 256 n values of this block; thread t handles n_local = t.
    const int m4 = tid >> 2;      // which float4 group
    const int j  = tid & 3;       // component

    float a1 = 0.f, a2 = 0.f;
    #pragma unroll
    for (int ss = 0; ss < SEGS; ++ss) {
        const float* p1 = (const float*)&sL1[ss][m4];
        const float* p2 = (const float*)&sL2[ss][m4];
        a1 += p1[j];
        a2 += p2[j];
    }

    // pair index = bp*N + nq*256 + tid ; out layout [l1, l2, l1] per pair
    const size_t pair = (size_t)bp * N + (size_t)nq * 256 + tid;
    const size_t o = pair * 3;
    __stcs(out + o + 0, a1);
    __stcs(out + o + 1, a2);
    __stcs(out + o + 2, a1);
}

extern "C" void kernel_launch(void* const* d_in, const int* in_sizes, int n_in,
                              void* d_out, int out_size) {
    const float4* x = (const float4*)d_in[0];
    const float4* y = (const float4*)d_in[1];
    float* out = (float*)d_out;

    sim_measure_kernel<<<BLOCKS, 256>>>(x, y, out);
}